// round 16
// baseline (speedup 1.0000x reference)
#include <cuda_runtime.h>
#include <cuda_bf16.h>
#include <math.h>
#include <stdint.h>

#define N_NODES 50000
#define N_EDGES 600000
#define N_BONDS 600000
#define H 128
#define NH 8

// ---------------- scratch ----------------
__device__ float    g_he0 [(size_t)N_EDGES * H];
__device__ float    g_agg [(size_t)N_EDGES * H];   // bond agg, then reused for xj
__device__ float    g_agg2[(size_t)N_NODES * H];
__device__ float    g_ex  [(size_t)N_EDGES * NH];
__device__ float    g_den [(size_t)N_NODES * NH];
__device__ unsigned char g_wsplit[10 * 2 * 32768];

__device__ __forceinline__ void split_bf16(float v, unsigned short& hi, unsigned short& lo) {
    __nv_bfloat16 h = __float2bfloat16_rn(v);
    float r = v - __bfloat162float(h);
    __nv_bfloat16 l = __float2bfloat16_rn(r);
    hi = __bfloat16_as_ushort(h);
    lo = __bfloat16_as_ushort(l);
}
__device__ __forceinline__ uint32_t smem_u32(const void* p) {
    uint32_t a;
    asm("{ .reg .u64 t; cvta.to.shared.u64 t, %1; cvt.u32.u64 %0, t; }" : "=r"(a) : "l"(p));
    return a;
}
__device__ __forceinline__ void mma_bf16(float* d, const unsigned* a, unsigned b0, unsigned b1) {
    asm volatile(
        "mma.sync.aligned.m16n8k16.row.col.f32.bf16.bf16.f32 "
        "{%0,%1,%2,%3}, {%4,%5,%6,%7}, {%8,%9}, {%0,%1,%2,%3};"
        : "+f"(d[0]), "+f"(d[1]), "+f"(d[2]), "+f"(d[3])
        : "r"(a[0]), "r"(a[1]), "r"(a[2]), "r"(a[3]), "r"(b0), "r"(b1));
}
__device__ __forceinline__ void ldmx4(unsigned& r0, unsigned& r1, unsigned& r2, unsigned& r3,
                                      uint32_t addr) {
    asm volatile("ldmatrix.sync.aligned.m8n8.x4.shared.b16 {%0,%1,%2,%3}, [%4];"
                 : "=r"(r0), "=r"(r1), "=r"(r2), "=r"(r3) : "r"(addr));
}
__device__ __forceinline__ void red_add_v4(float* ptr, float a, float b, float c, float d) {
    asm volatile("red.global.add.v4.f32 [%0], {%1,%2,%3,%4};"
                 :: "l"(ptr), "f"(a), "f"(b), "f"(c), "f"(d) : "memory");
}
#define CP_ASYNC16(sm_, gp_) \
    asm volatile("cp.async.ca.shared.global [%0], [%1], 16;" :: "r"(sm_), "l"(gp_))
#define CP_COMMIT() asm volatile("cp.async.commit_group;" ::: "memory")
#define CP_WAIT0()  asm volatile("cp.async.wait_group 0;" ::: "memory")

__global__ __launch_bounds__(256) void zero_scratch() {
    size_t idx = (size_t)blockIdx.x * 256 + threadIdx.x;
    if (idx < (size_t)N_EDGES * H) g_agg[idx] = 0.f;
    if (idx < (size_t)N_NODES * H) g_agg2[idx] = 0.f;
    if (idx < (size_t)N_NODES * NH) g_den[idx] = 0.f;
}

// ---------------- weight prep ----------------
struct WSrcs { const float* p[10]; };

__global__ __launch_bounds__(256) void prep_all(WSrcs ws, unsigned char* dst)
{
    int slice = blockIdx.x >> 6;
    int e = (blockIdx.x & 63) * 256 + threadIdx.x;
    int k = e >> 7;
    int n = e & 127;
    float v = ws.p[slice][k * 128 + n];
    unsigned short h, l;
    split_bf16(v, h, l);
    unsigned short* dsthi = (unsigned short*)(dst + (size_t)slice * 65536);
    unsigned short* dstlo = (unsigned short*)(dst + (size_t)slice * 65536 + 32768);
    dsthi[n * 128 + k] = h;
    dstlo[n * 128 + k] = l;
}

// ==================================================================================
// split-bf16 HMMA GEMM: BM=128, BN=128, BK=32, 256 thr, ldmatrix + double buffer,
// 2 CTAs/SM.  ATTN=1: fused attention-beta epilogue (he GEMM only).
// ==================================================================================
#define SROW 40
#define PLANE (128 * SROW)
#define SMEM_GEMM_BYTES (2 * 2 * PLANE * 2 * 2)

template<int NSEG, int ATTN>
__global__ __launch_bounds__(256, 2)
void mma_gemm(
    int M,
    const float* __restrict__ S0, const int* __restrict__ I0,
    const float* __restrict__ S1, const int* __restrict__ I1,
    const float* __restrict__ S2,
    const unsigned char* __restrict__ wsl,
    const float* __restrict__ B0, const float* __restrict__ B1, const float* __restrict__ B2,
    const float* __restrict__ residual,
    float* __restrict__ out,
    const float* __restrict__ xattn, const int* __restrict__ asrc, const int* __restrict__ atgt,
    const float* __restrict__ attnw, const float* __restrict__ attnb)
{
    extern __shared__ __align__(16) unsigned short smem[];
    unsigned short* sA = smem;
    unsigned short* sB = smem + 2 * 2 * PLANE;
    __shared__ int sI0[128], sI1[128];
    __shared__ float sbias[128];
    __shared__ float sw[32];

    const int t = threadIdx.x;
    const int lane = t & 31;
    const int wid = t >> 5;
    const int warp_m = wid & 3;
    const int warp_n = wid >> 2;
    const int blockRow = blockIdx.x * 128;

    if (t < 128) {
        int r = blockRow + t;
        if (r >= M) r = M - 1;
        sI0[t] = I0 ? I0[r] : r;
        sI1[t] = I1 ? I1[r] : r;
        float b = B0[t];
        if (B1) b += B1[t];
        if (B2) b += B2[t];
        sbias[t] = b;
    }
    if (ATTN && t < 32) sw[t] = attnw[t];
    __syncthreads();

    const int arow = t >> 1;
    const int aseg = t & 1;
    const int arow_cl = (blockRow + arow < M) ? (blockRow + arow) : (M - 1);
    const int bh = t >> 7;
    const int bn = t & 127;

    const uint32_t sa_u32 = smem_u32(sA);
    const uint32_t sb_u32 = smem_u32(sB);
    const uint32_t sb_row = sb_u32 + (uint32_t)bh * PLANE * 2 + (uint32_t)bn * SROW * 2;

    float d[2][8][4];
#pragma unroll
    for (int mt = 0; mt < 2; ++mt)
#pragma unroll
        for (int nt = 0; nt < 8; ++nt)
#pragma unroll
            for (int c = 0; c < 4; ++c) d[mt][nt][c] = 0.f;

    const int NITER = NSEG * 4;

    unsigned uhA[8], ulA[8];

#define LOAD_A(kt_) do { \
        int s_ = (kt_) >> 2; \
        const float* rp_; \
        if (s_ == 0)      rp_ = S0 + (size_t)sI0[arow] * H; \
        else if (s_ == 1) rp_ = S1 + (size_t)sI1[arow] * H; \
        else              rp_ = S2 + (size_t)arow_cl * H; \
        int kloc_ = ((kt_) & 3) * 32 + aseg * 16; \
        _Pragma("unroll") \
        for (int i_ = 0; i_ < 4; ++i_) { \
            float4 v_ = *(const float4*)(rp_ + kloc_ + i_ * 4); \
            unsigned short h0_, l0_, h1_, l1_; \
            split_bf16(v_.x, h0_, l0_); split_bf16(v_.y, h1_, l1_); \
            uhA[i_ * 2]     = (unsigned)h0_ | ((unsigned)h1_ << 16); \
            ulA[i_ * 2]     = (unsigned)l0_ | ((unsigned)l1_ << 16); \
            split_bf16(v_.z, h0_, l0_); split_bf16(v_.w, h1_, l1_); \
            uhA[i_ * 2 + 1] = (unsigned)h0_ | ((unsigned)h1_ << 16); \
            ulA[i_ * 2 + 1] = (unsigned)l0_ | ((unsigned)l1_ << 16); \
        } \
    } while (0)

#define STORE_A(stage_) do { \
        unsigned short* ah_ = sA + (size_t)(stage_) * 2 * PLANE + (size_t)arow * SROW + aseg * 16; \
        unsigned short* al_ = ah_ + PLANE; \
        *(uint4*)(ah_)     = make_uint4(uhA[0], uhA[1], uhA[2], uhA[3]); \
        *(uint4*)(ah_ + 8) = make_uint4(uhA[4], uhA[5], uhA[6], uhA[7]); \
        *(uint4*)(al_)     = make_uint4(ulA[0], ulA[1], ulA[2], ulA[3]); \
        *(uint4*)(al_ + 8) = make_uint4(ulA[4], ulA[5], ulA[6], ulA[7]); \
    } while (0)

#define LOAD_B(kt_, stage_) do { \
        int s_ = (kt_) >> 2; \
        const unsigned char* src_ = wsl + (size_t)s_ * 65536 + (size_t)bh * 32768 \
                                  + (size_t)bn * 256 + (size_t)((kt_) & 3) * 64; \
        uint32_t dst_ = sb_row + (uint32_t)(stage_) * 2 * PLANE * 2; \
        CP_ASYNC16(dst_,      src_); \
        CP_ASYNC16(dst_ + 16, src_ + 16); \
        CP_ASYNC16(dst_ + 32, src_ + 32); \
        CP_ASYNC16(dst_ + 48, src_ + 48); \
        CP_COMMIT(); \
    } while (0)

    LOAD_B(0, 0);
    LOAD_A(0);
    STORE_A(0);
    CP_WAIT0();
    __syncthreads();

    for (int kt = 0; kt < NITER; ++kt) {
        const int stage = kt & 1;
        if (kt + 1 < NITER) {
            LOAD_B(kt + 1, (kt + 1) & 1);
            LOAD_A(kt + 1);
        }

        const uint32_t aplane = sa_u32 + (uint32_t)stage * 2 * PLANE * 2;
        const uint32_t bplane = sb_u32 + (uint32_t)stage * 2 * PLANE * 2;
        const uint32_t lrow = (lane & 15);
        const uint32_t lcol = (lane >> 4) * 8;

#pragma unroll
        for (int ks = 0; ks < 2; ++ks) {
            unsigned af[2][2][4];
#pragma unroll
            for (int hl = 0; hl < 2; ++hl)
#pragma unroll
                for (int mt = 0; mt < 2; ++mt) {
                    uint32_t row = warp_m * 32 + mt * 16 + lrow;
                    uint32_t addr = aplane + (uint32_t)hl * PLANE * 2
                                  + (row * SROW + ks * 16 + lcol) * 2;
                    ldmx4(af[hl][mt][0], af[hl][mt][1], af[hl][mt][2], af[hl][mt][3], addr);
                }
            unsigned bf[2][8][2];
#pragma unroll
            for (int hl = 0; hl < 2; ++hl)
#pragma unroll
                for (int pr = 0; pr < 4; ++pr) {
                    uint32_t row = warp_n * 64 + pr * 16 + lrow;
                    uint32_t addr = bplane + (uint32_t)hl * PLANE * 2
                                  + (row * SROW + ks * 16 + lcol) * 2;
                    unsigned r0, r1, r2, r3;
                    ldmx4(r0, r1, r2, r3, addr);
                    bf[hl][pr * 2][0] = r0;  bf[hl][pr * 2][1] = r2;
                    bf[hl][pr * 2 + 1][0] = r1;  bf[hl][pr * 2 + 1][1] = r3;
                }
#pragma unroll
            for (int nt = 0; nt < 8; ++nt)
#pragma unroll
                for (int mt = 0; mt < 2; ++mt) {
                    mma_bf16(d[mt][nt], af[0][mt], bf[0][nt][0], bf[0][nt][1]);
                    mma_bf16(d[mt][nt], af[1][mt], bf[0][nt][0], bf[0][nt][1]);
                    mma_bf16(d[mt][nt], af[0][mt], bf[1][nt][0], bf[1][nt][1]);
                }
        }

        if (kt + 1 < NITER) {
            STORE_A((kt + 1) & 1);
            CP_WAIT0();
            __syncthreads();
        }
    }
#undef LOAD_A
#undef STORE_A
#undef LOAD_B

    // ---- epilogue ----
#pragma unroll
    for (int mt = 0; mt < 2; ++mt) {
#pragma unroll
        for (int half = 0; half < 2; ++half) {
            int r = warp_m * 32 + mt * 16 + (lane >> 2) + half * 8;
            int grow = blockRow + r;
            if (ATTN == 0) {
                if (grow >= M) continue;
#pragma unroll
                for (int nt = 0; nt < 8; ++nt) {
                    int gc = warp_n * 64 + nt * 8 + (lane & 3) * 2;
                    float v0 = fmaxf(d[mt][nt][half * 2 + 0] + sbias[gc], 0.f);
                    float v1 = fmaxf(d[mt][nt][half * 2 + 1] + sbias[gc + 1], 0.f);
                    if (residual) {
                        float2 rr = *(const float2*)(residual + (size_t)grow * H + gc);
                        v0 += rr.x;
                        v1 += rr.y;
                    }
                    *(float2*)(out + (size_t)grow * H + gc) = make_float2(v0, v1);
                }
            } else {
                // fused he + attention-beta epilogue (uniform warp execution for shfl)
                bool valid = (grow < M);
                int grc = valid ? grow : (M - 1);
                int s = asrc[grc];
                int g = atgt[grc];
                float bsum[4] = {0.f, 0.f, 0.f, 0.f};
#pragma unroll
                for (int nt = 0; nt < 8; ++nt) {
                    int gc = warp_n * 64 + nt * 8 + (lane & 3) * 2;
                    float v0 = fmaxf(d[mt][nt][half * 2 + 0] + sbias[gc], 0.f);
                    float v1 = fmaxf(d[mt][nt][half * 2 + 1] + sbias[gc + 1], 0.f);
                    float2 xsv = *(const float2*)(xattn + (size_t)s * H + gc);
                    float2 xtv = *(const float2*)(xattn + (size_t)g * H + gc);
                    float xj0 = xsv.x * v0;
                    float xj1 = xsv.y * v1;
                    if (valid) {
                        *(float2*)(out + (size_t)grow * H + gc) = make_float2(v0, v1);
                        *(float2*)(g_agg + (size_t)grow * H + gc) = make_float2(xj0, xj1);
                    }
                    int dd = gc & 15;
                    bsum[nt >> 1] += xj0 * sw[dd] + xtv.x * sw[16 + dd]
                                   + xj1 * sw[dd + 1] + xtv.y * sw[16 + dd + 1];
                }
                float b0a = attnb[0];
#pragma unroll
                for (int hh = 0; hh < 4; ++hh) {
                    float p = bsum[hh];
                    p += __shfl_xor_sync(0xffffffffu, p, 1);
                    p += __shfl_xor_sync(0xffffffffu, p, 2);
                    if ((lane & 3) == 0 && valid) {
                        int head = warp_n * 4 + hh;
                        float b = p + b0a;
                        b = (b > 0.f) ? b : 0.01f * b;
                        float ex = expf(b);
                        g_ex[(size_t)grow * NH + head] = ex;
                        atomicAdd(&g_den[(size_t)g * NH + head], ex);
                    }
                }
            }
        }
    }
}

// ---------------- bond scatter (vector red) ----------------
__global__ __launch_bounds__(256) void scatter_bond(
    const int* __restrict__ bsrc, const int* __restrict__ btgt,
    const float* __restrict__ battr)
{
    size_t idx = (size_t)blockIdx.x * 256 + threadIdx.x;
    int b = (int)(idx >> 5);
    int c = (int)(idx & 31) * 4;
    int s = bsrc[b];
    int g = btgt[b];
    float4 hv = *(const float4*)(g_he0 + (size_t)s * H + c);
    float4 bv = *(const float4*)(battr + (size_t)b * H + c);
    red_add_v4(g_agg + (size_t)g * H + c,
               hv.x * bv.x, hv.y * bv.y, hv.z * bv.z, hv.w * bv.w);
}

// ---------------- attention scatter: agg2[tgt] += alpha * xj (cached) ----------------
__global__ __launch_bounds__(256) void attn_scatter(
    const int* __restrict__ tgt)
{
    size_t idx = (size_t)blockIdx.x * 256 + threadIdx.x;
    int e = (int)(idx >> 5);
    int c = (int)(idx & 31) * 4;
    int h = c >> 4;
    int g = tgt[e];
    float alpha = g_ex[(size_t)e * NH + h] / (g_den[(size_t)g * NH + h] + 1e-16f);
    float4 xj = *(const float4*)(g_agg + (size_t)e * H + c);
    red_add_v4(g_agg2 + (size_t)g * H + c,
               alpha * xj.x, alpha * xj.y, alpha * xj.z, alpha * xj.w);
}

// ---------------- launch ----------------
extern "C" void kernel_launch(void* const* d_in, const int* in_sizes, int n_in,
                              void* d_out, int out_size)
{
    const float* x     = (const float*)d_in[0];
    const int*   ei    = (const int*)d_in[1];
    const float* eattr = (const float*)d_in[2];
    const int*   bei   = (const int*)d_in[3];
    const float* battr = (const float*)d_in[4];
    const float* W_n2e = (const float*)d_in[5];
    const float* b_n2e = (const float*)d_in[6];
    const float* A1w   = (const float*)d_in[7];
    const float* A1b   = (const float*)d_in[8];
    const float* A2w   = (const float*)d_in[9];
    const float* A2b   = (const float*)d_in[10];
    const float* A3w   = (const float*)d_in[11];
    const float* A3b   = (const float*)d_in[12];
    const float* Wc1w  = (const float*)d_in[13];
    const float* Wc1b  = (const float*)d_in[14];
    const float* attnw = (const float*)d_in[15];
    const float* attnb = (const float*)d_in[16];
    const float* Wc2w  = (const float*)d_in[17];
    const float* Wc2b  = (const float*)d_in[18];

    float* out    = (float*)d_out;
    float* out_hx = out;
    float* out_he = out + (size_t)N_NODES * H;
    float* out_ha = out_he + (size_t)N_EDGES * H;

    const int* src  = ei;
    const int* tgt  = ei + N_EDGES;
    const int* bsrc = bei;
    const int* btgt = bei + N_BONDS;

    float *p_he0, *p_agg, *p_agg2;
    unsigned char* p_w;
    cudaGetSymbolAddress((void**)&p_he0,  g_he0);
    cudaGetSymbolAddress((void**)&p_agg,  g_agg);
    cudaGetSymbolAddress((void**)&p_agg2, g_agg2);
    cudaGetSymbolAddress((void**)&p_w,    g_wsplit);

    static cudaStream_t s1 = nullptr;
    static cudaEvent_t evStart, evZ, evA, evB;
    if (!s1) {
        cudaStreamCreateWithFlags(&s1, cudaStreamNonBlocking);
        cudaEventCreateWithFlags(&evStart, cudaEventDisableTiming);
        cudaEventCreateWithFlags(&evZ, cudaEventDisableTiming);
        cudaEventCreateWithFlags(&evA, cudaEventDisableTiming);
        cudaEventCreateWithFlags(&evB, cudaEventDisableTiming);
        cudaFuncSetAttribute(mma_gemm<2, 0>, cudaFuncAttributeMaxDynamicSharedMemorySize, SMEM_GEMM_BYTES);
        cudaFuncSetAttribute(mma_gemm<2, 1>, cudaFuncAttributeMaxDynamicSharedMemorySize, SMEM_GEMM_BYTES);
        cudaFuncSetAttribute(mma_gemm<3, 0>, cudaFuncAttributeMaxDynamicSharedMemorySize, SMEM_GEMM_BYTES);
    }

    WSrcs ws;
    ws.p[0] = W_n2e; ws.p[1] = W_n2e + 128 * H; ws.p[2] = W_n2e + 256 * H;
    ws.p[3] = Wc1w;  ws.p[4] = Wc1w + 128 * H;
    ws.p[5] = A1w;   ws.p[6] = A2w;   ws.p[7] = A3w;
    ws.p[8] = Wc2w;  ws.p[9] = Wc2w + 128 * H;
    prep_all<<<640, 256>>>(ws, p_w);

    cudaEventRecord(evStart, 0);
    cudaStreamWaitEvent(s1, evStart, 0);
    zero_scratch<<<(N_EDGES * H) / 256, 256, 0, s1>>>();
    cudaEventRecord(evZ, s1);

    // 1) he0 = relu(cat(x[src], x[tgt], edge_attr) @ W_n2e + b)   [main]
    mma_gemm<3, 0><<<(N_EDGES + 127) / 128, 256, SMEM_GEMM_BYTES>>>(
        N_EDGES, x, src, x, tgt, eattr, p_w + 0 * 65536,
        b_n2e, nullptr, nullptr, nullptr, p_he0,
        nullptr, nullptr, nullptr, nullptr, nullptr);
    cudaEventRecord(evA, 0);

    // 4) ha GEMM on side stream, concurrent with scatter/he/attention
    cudaStreamWaitEvent(s1, evA, 0);
    mma_gemm<3, 0><<<(N_BONDS + 127) / 128, 256, SMEM_GEMM_BYTES, s1>>>(
        N_BONDS, p_he0, bsrc, p_he0, btgt, battr, p_w + 5 * 65536,
        A1b, A2b, A3b, battr, out_ha,
        nullptr, nullptr, nullptr, nullptr, nullptr);
    cudaEventRecord(evB, s1);

    cudaStreamWaitEvent(0, evZ, 0);

    // 2) agg[btgt] += he0[bsrc] * bond_attr
    scatter_bond<<<(N_BONDS * 32) / 256, 256>>>(bsrc, btgt, battr);

    // 3) he = relu(cat(he0, agg) @ Wc1 + b)  + fused attention-beta epilogue
    mma_gemm<2, 1><<<(N_EDGES + 127) / 128, 256, SMEM_GEMM_BYTES>>>(
        N_EDGES, p_he0, nullptr, p_agg, nullptr, nullptr, p_w + 3 * 65536,
        Wc1b, nullptr, nullptr, nullptr, out_he,
        x, src, tgt, attnw, attnb);

    // 5) agg2[tgt] += alpha * xj
    attn_scatter<<<(N_EDGES * 32) / 256, 256>>>(tgt);

    // 6) hx = relu(cat(x, agg2) @ Wc2 + b)
    mma_gemm<2, 0><<<(N_NODES + 127) / 128, 256, SMEM_GEMM_BYTES>>>(
        N_NODES, x, nullptr, p_agg2, nullptr, nullptr, p_w + 8 * 65536,
        Wc2b, nullptr, nullptr, nullptr, out_hx,
        nullptr, nullptr, nullptr, nullptr, nullptr);

    cudaStreamWaitEvent(0, evB, 0);
}

// round 17
// speedup vs baseline: 1.4906x; 1.4906x over previous
#include <cuda_runtime.h>
#include <cuda_bf16.h>
#include <math.h>
#include <stdint.h>

#define N_NODES 50000
#define N_EDGES 600000
#define N_BONDS 600000
#define H 128
#define NH 8

// ---------------- scratch ----------------
__device__ float    g_he0 [(size_t)N_EDGES * H];
__device__ float    g_agg [(size_t)N_EDGES * H];   // bond agg, then reused for xj
__device__ float    g_agg2[(size_t)N_NODES * H];
__device__ float    g_tmp [(size_t)N_NODES * H];   // hx partial (x @ Wc2[0:128])
__device__ float    g_ex  [(size_t)N_EDGES * NH];
__device__ float    g_den [(size_t)N_NODES * NH];
__device__ unsigned char g_wsplit[10 * 2 * 32768];

__device__ __forceinline__ void split_bf16(float v, unsigned short& hi, unsigned short& lo) {
    __nv_bfloat16 h = __float2bfloat16_rn(v);
    float r = v - __bfloat162float(h);
    __nv_bfloat16 l = __float2bfloat16_rn(r);
    hi = __bfloat16_as_ushort(h);
    lo = __bfloat16_as_ushort(l);
}
__device__ __forceinline__ uint32_t smem_u32(const void* p) {
    uint32_t a;
    asm("{ .reg .u64 t; cvta.to.shared.u64 t, %1; cvt.u32.u64 %0, t; }" : "=r"(a) : "l"(p));
    return a;
}
__device__ __forceinline__ void mma_bf16(float* d, const unsigned* a, unsigned b0, unsigned b1) {
    asm volatile(
        "mma.sync.aligned.m16n8k16.row.col.f32.bf16.bf16.f32 "
        "{%0,%1,%2,%3}, {%4,%5,%6,%7}, {%8,%9}, {%0,%1,%2,%3};"
        : "+f"(d[0]), "+f"(d[1]), "+f"(d[2]), "+f"(d[3])
        : "r"(a[0]), "r"(a[1]), "r"(a[2]), "r"(a[3]), "r"(b0), "r"(b1));
}
__device__ __forceinline__ void ldmx4(unsigned& r0, unsigned& r1, unsigned& r2, unsigned& r3,
                                      uint32_t addr) {
    asm volatile("ldmatrix.sync.aligned.m8n8.x4.shared.b16 {%0,%1,%2,%3}, [%4];"
                 : "=r"(r0), "=r"(r1), "=r"(r2), "=r"(r3) : "r"(addr));
}
__device__ __forceinline__ void red_add_v4(float* ptr, float a, float b, float c, float d) {
    asm volatile("red.global.add.v4.f32 [%0], {%1,%2,%3,%4};"
                 :: "l"(ptr), "f"(a), "f"(b), "f"(c), "f"(d) : "memory");
}
#define CP_ASYNC16(sm_, gp_) \
    asm volatile("cp.async.ca.shared.global [%0], [%1], 16;" :: "r"(sm_), "l"(gp_))
#define CP_COMMIT() asm volatile("cp.async.commit_group;" ::: "memory")
#define CP_WAIT0()  asm volatile("cp.async.wait_group 0;" ::: "memory")

__global__ __launch_bounds__(256) void zero_scratch() {
    size_t idx = (size_t)blockIdx.x * 256 + threadIdx.x;
    if (idx < (size_t)N_EDGES * H) g_agg[idx] = 0.f;
    if (idx < (size_t)N_NODES * H) g_agg2[idx] = 0.f;
    if (idx < (size_t)N_NODES * NH) g_den[idx] = 0.f;
}

// ---------------- weight prep ----------------
struct WSrcs { const float* p[10]; };

__global__ __launch_bounds__(256) void prep_all(WSrcs ws, unsigned char* dst)
{
    int slice = blockIdx.x >> 6;
    int e = (blockIdx.x & 63) * 256 + threadIdx.x;
    int k = e >> 7;
    int n = e & 127;
    float v = ws.p[slice][k * 128 + n];
    unsigned short h, l;
    split_bf16(v, h, l);
    unsigned short* dsthi = (unsigned short*)(dst + (size_t)slice * 65536);
    unsigned short* dstlo = (unsigned short*)(dst + (size_t)slice * 65536 + 32768);
    dsthi[n * 128 + k] = h;
    dstlo[n * 128 + k] = l;
}

// ---------------- invert attention denominators in place ----------------
__global__ __launch_bounds__(256) void inv_den()
{
    int idx = blockIdx.x * 256 + threadIdx.x;
    if (idx < N_NODES * NH) g_den[idx] = 1.f / (g_den[idx] + 1e-16f);
}

// ==================================================================================
// split-bf16 HMMA GEMM: BM=128, BN=128, BK=32, 256 thr, ldmatrix + double buffer,
// 2 CTAs/SM.  EPI: 0 = relu(acc+bias)(+res post), 1 = raw acc, 2 = relu(acc+bias+res)
// ==================================================================================
#define SROW 40
#define PLANE (128 * SROW)
#define SMEM_GEMM_BYTES (2 * 2 * PLANE * 2 * 2)

template<int NSEG, int EPI>
__global__ __launch_bounds__(256, 2)
void mma_gemm(
    int M,
    const float* __restrict__ S0, const int* __restrict__ I0,
    const float* __restrict__ S1, const int* __restrict__ I1,
    const float* __restrict__ S2,
    const unsigned char* __restrict__ wsl,
    const float* __restrict__ B0, const float* __restrict__ B1, const float* __restrict__ B2,
    const float* __restrict__ residual,
    float* __restrict__ out)
{
    extern __shared__ __align__(16) unsigned short smem[];
    unsigned short* sA = smem;
    unsigned short* sB = smem + 2 * 2 * PLANE;
    __shared__ int sI0[128], sI1[128];
    __shared__ float sbias[128];

    const int t = threadIdx.x;
    const int lane = t & 31;
    const int wid = t >> 5;
    const int warp_m = wid & 3;
    const int warp_n = wid >> 2;
    const int blockRow = blockIdx.x * 128;

    if (t < 128) {
        int r = blockRow + t;
        if (r >= M) r = M - 1;
        sI0[t] = I0 ? I0[r] : r;
        sI1[t] = (NSEG > 1) ? (I1 ? I1[r] : r) : 0;
        float b = B0[t];
        if (B1) b += B1[t];
        if (B2) b += B2[t];
        sbias[t] = b;
    }
    __syncthreads();

    const int arow = t >> 1;
    const int aseg = t & 1;
    const int arow_cl = (blockRow + arow < M) ? (blockRow + arow) : (M - 1);
    const int bh = t >> 7;
    const int bn = t & 127;

    const uint32_t sa_u32 = smem_u32(sA);
    const uint32_t sb_u32 = smem_u32(sB);
    const uint32_t sb_row = sb_u32 + (uint32_t)bh * PLANE * 2 + (uint32_t)bn * SROW * 2;

    float d[2][8][4];
#pragma unroll
    for (int mt = 0; mt < 2; ++mt)
#pragma unroll
        for (int nt = 0; nt < 8; ++nt)
#pragma unroll
            for (int c = 0; c < 4; ++c) d[mt][nt][c] = 0.f;

    const int NITER = NSEG * 4;

    unsigned uhA[8], ulA[8];

#define LOAD_A(kt_) do { \
        int s_ = (kt_) >> 2; \
        const float* rp_; \
        if (s_ == 0)      rp_ = S0 + (size_t)sI0[arow] * H; \
        else if (s_ == 1) rp_ = S1 + (size_t)sI1[arow] * H; \
        else              rp_ = S2 + (size_t)arow_cl * H; \
        int kloc_ = ((kt_) & 3) * 32 + aseg * 16; \
        _Pragma("unroll") \
        for (int i_ = 0; i_ < 4; ++i_) { \
            float4 v_ = *(const float4*)(rp_ + kloc_ + i_ * 4); \
            unsigned short h0_, l0_, h1_, l1_; \
            split_bf16(v_.x, h0_, l0_); split_bf16(v_.y, h1_, l1_); \
            uhA[i_ * 2]     = (unsigned)h0_ | ((unsigned)h1_ << 16); \
            ulA[i_ * 2]     = (unsigned)l0_ | ((unsigned)l1_ << 16); \
            split_bf16(v_.z, h0_, l0_); split_bf16(v_.w, h1_, l1_); \
            uhA[i_ * 2 + 1] = (unsigned)h0_ | ((unsigned)h1_ << 16); \
            ulA[i_ * 2 + 1] = (unsigned)l0_ | ((unsigned)l1_ << 16); \
        } \
    } while (0)

#define STORE_A(stage_) do { \
        unsigned short* ah_ = sA + (size_t)(stage_) * 2 * PLANE + (size_t)arow * SROW + aseg * 16; \
        unsigned short* al_ = ah_ + PLANE; \
        *(uint4*)(ah_)     = make_uint4(uhA[0], uhA[1], uhA[2], uhA[3]); \
        *(uint4*)(ah_ + 8) = make_uint4(uhA[4], uhA[5], uhA[6], uhA[7]); \
        *(uint4*)(al_)     = make_uint4(ulA[0], ulA[1], ulA[2], ulA[3]); \
        *(uint4*)(al_ + 8) = make_uint4(ulA[4], ulA[5], ulA[6], ulA[7]); \
    } while (0)

#define LOAD_B(kt_, stage_) do { \
        int s_ = (kt_) >> 2; \
        const unsigned char* src_ = wsl + (size_t)s_ * 65536 + (size_t)bh * 32768 \
                                  + (size_t)bn * 256 + (size_t)((kt_) & 3) * 64; \
        uint32_t dst_ = sb_row + (uint32_t)(stage_) * 2 * PLANE * 2; \
        CP_ASYNC16(dst_,      src_); \
        CP_ASYNC16(dst_ + 16, src_ + 16); \
        CP_ASYNC16(dst_ + 32, src_ + 32); \
        CP_ASYNC16(dst_ + 48, src_ + 48); \
        CP_COMMIT(); \
    } while (0)

    LOAD_B(0, 0);
    LOAD_A(0);
    STORE_A(0);
    CP_WAIT0();
    __syncthreads();

    for (int kt = 0; kt < NITER; ++kt) {
        const int stage = kt & 1;
        if (kt + 1 < NITER) {
            LOAD_B(kt + 1, (kt + 1) & 1);
            LOAD_A(kt + 1);
        }

        const uint32_t aplane = sa_u32 + (uint32_t)stage * 2 * PLANE * 2;
        const uint32_t bplane = sb_u32 + (uint32_t)stage * 2 * PLANE * 2;
        const uint32_t lrow = (lane & 15);
        const uint32_t lcol = (lane >> 4) * 8;

#pragma unroll
        for (int ks = 0; ks < 2; ++ks) {
            unsigned af[2][2][4];
#pragma unroll
            for (int hl = 0; hl < 2; ++hl)
#pragma unroll
                for (int mt = 0; mt < 2; ++mt) {
                    uint32_t row = warp_m * 32 + mt * 16 + lrow;
                    uint32_t addr = aplane + (uint32_t)hl * PLANE * 2
                                  + (row * SROW + ks * 16 + lcol) * 2;
                    ldmx4(af[hl][mt][0], af[hl][mt][1], af[hl][mt][2], af[hl][mt][3], addr);
                }
            unsigned bf[2][8][2];
#pragma unroll
            for (int hl = 0; hl < 2; ++hl)
#pragma unroll
                for (int pr = 0; pr < 4; ++pr) {
                    uint32_t row = warp_n * 64 + pr * 16 + lrow;
                    uint32_t addr = bplane + (uint32_t)hl * PLANE * 2
                                  + (row * SROW + ks * 16 + lcol) * 2;
                    unsigned r0, r1, r2, r3;
                    ldmx4(r0, r1, r2, r3, addr);
                    bf[hl][pr * 2][0] = r0;  bf[hl][pr * 2][1] = r2;
                    bf[hl][pr * 2 + 1][0] = r1;  bf[hl][pr * 2 + 1][1] = r3;
                }
#pragma unroll
            for (int nt = 0; nt < 8; ++nt)
#pragma unroll
                for (int mt = 0; mt < 2; ++mt) {
                    mma_bf16(d[mt][nt], af[0][mt], bf[0][nt][0], bf[0][nt][1]);
                    mma_bf16(d[mt][nt], af[1][mt], bf[0][nt][0], bf[0][nt][1]);
                    mma_bf16(d[mt][nt], af[0][mt], bf[1][nt][0], bf[1][nt][1]);
                }
        }

        if (kt + 1 < NITER) {
            STORE_A((kt + 1) & 1);
            CP_WAIT0();
            __syncthreads();
        }
    }
#undef LOAD_A
#undef STORE_A
#undef LOAD_B

#pragma unroll
    for (int mt = 0; mt < 2; ++mt) {
#pragma unroll
        for (int half = 0; half < 2; ++half) {
            int r = warp_m * 32 + mt * 16 + (lane >> 2) + half * 8;
            int grow = blockRow + r;
            if (grow >= M) continue;
#pragma unroll
            for (int nt = 0; nt < 8; ++nt) {
                int gc = warp_n * 64 + nt * 8 + (lane & 3) * 2;
                float a0 = d[mt][nt][half * 2 + 0];
                float a1 = d[mt][nt][half * 2 + 1];
                float v0, v1;
                if (EPI == 1) {
                    v0 = a0; v1 = a1;
                } else if (EPI == 2) {
                    float2 rr = *(const float2*)(residual + (size_t)grow * H + gc);
                    v0 = fmaxf(a0 + sbias[gc] + rr.x, 0.f);
                    v1 = fmaxf(a1 + sbias[gc + 1] + rr.y, 0.f);
                } else {
                    v0 = fmaxf(a0 + sbias[gc], 0.f);
                    v1 = fmaxf(a1 + sbias[gc + 1], 0.f);
                    if (residual) {
                        float2 rr = *(const float2*)(residual + (size_t)grow * H + gc);
                        v0 += rr.x;
                        v1 += rr.y;
                    }
                }
                *(float2*)(out + (size_t)grow * H + gc) = make_float2(v0, v1);
            }
        }
    }
}

// ---------------- bond scatter (vector red) ----------------
__global__ __launch_bounds__(256) void scatter_bond(
    const int* __restrict__ bsrc, const int* __restrict__ btgt,
    const float* __restrict__ battr)
{
    size_t idx = (size_t)blockIdx.x * 256 + threadIdx.x;
    int b = (int)(idx >> 5);
    int c = (int)(idx & 31) * 4;
    int s = bsrc[b];
    int g = btgt[b];
    float4 hv = *(const float4*)(g_he0 + (size_t)s * H + c);
    float4 bv = *(const float4*)(battr + (size_t)b * H + c);
    red_add_v4(g_agg + (size_t)g * H + c,
               hv.x * bv.x, hv.y * bv.y, hv.z * bv.z, hv.w * bv.w);
}

// ---------------- attention pass 1: ex = exp(leaky(beta)), den += ex; caches xj ----------------
__global__ __launch_bounds__(256) void attn_beta(
    const float* __restrict__ x,
    const int* __restrict__ src, const int* __restrict__ tgt,
    const float* __restrict__ he,
    const float* __restrict__ attnw, const float* __restrict__ attnb)
{
    int gt = blockIdx.x * 256 + threadIdx.x;
    int e = gt >> 5;
    int lane = gt & 31;
    int s = src[e];
    int g = tgt[e];
    int c = lane * 4;
    int d = c & 15;
    float4 xs = *(const float4*)(x + (size_t)s * H + c);
    float4 hh = *(const float4*)(he + (size_t)e * H + c);
    float4 xt = *(const float4*)(x + (size_t)g * H + c);
    float4 xj = make_float4(xs.x * hh.x, xs.y * hh.y, xs.z * hh.z, xs.w * hh.w);
    *(float4*)(g_agg + (size_t)e * H + c) = xj;
    float p = xj.x * attnw[d]     + xt.x * attnw[16 + d]
            + xj.y * attnw[d + 1] + xt.y * attnw[17 + d]
            + xj.z * attnw[d + 2] + xt.z * attnw[18 + d]
            + xj.w * attnw[d + 3] + xt.w * attnw[19 + d];
    p += __shfl_xor_sync(0xffffffffu, p, 1);
    p += __shfl_xor_sync(0xffffffffu, p, 2);
    if ((lane & 3) == 0) {
        int h = lane >> 2;
        float b = p + attnb[0];
        b = (b > 0.f) ? b : 0.01f * b;
        float ex = expf(b);
        g_ex[(size_t)e * NH + h] = ex;
        atomicAdd(&g_den[(size_t)g * NH + h], ex);
    }
}

// ---------------- attention pass 2: agg2[tgt] += alpha * xj (den pre-inverted) ----------------
__global__ __launch_bounds__(256) void attn_scatter(
    const int* __restrict__ tgt)
{
    size_t idx = (size_t)blockIdx.x * 256 + threadIdx.x;
    int e = (int)(idx >> 5);
    int c = (int)(idx & 31) * 4;
    int h = c >> 4;
    int g = tgt[e];
    float alpha = g_ex[(size_t)e * NH + h] * g_den[(size_t)g * NH + h];
    float4 xj = *(const float4*)(g_agg + (size_t)e * H + c);
    red_add_v4(g_agg2 + (size_t)g * H + c,
               alpha * xj.x, alpha * xj.y, alpha * xj.z, alpha * xj.w);
}

// ---------------- launch ----------------
extern "C" void kernel_launch(void* const* d_in, const int* in_sizes, int n_in,
                              void* d_out, int out_size)
{
    const float* x     = (const float*)d_in[0];
    const int*   ei    = (const int*)d_in[1];
    const float* eattr = (const float*)d_in[2];
    const int*   bei   = (const int*)d_in[3];
    const float* battr = (const float*)d_in[4];
    const float* W_n2e = (const float*)d_in[5];
    const float* b_n2e = (const float*)d_in[6];
    const float* A1w   = (const float*)d_in[7];
    const float* A1b   = (const float*)d_in[8];
    const float* A2w   = (const float*)d_in[9];
    const float* A2b   = (const float*)d_in[10];
    const float* A3w   = (const float*)d_in[11];
    const float* A3b   = (const float*)d_in[12];
    const float* Wc1w  = (const float*)d_in[13];
    const float* Wc1b  = (const float*)d_in[14];
    const float* attnw = (const float*)d_in[15];
    const float* attnb = (const float*)d_in[16];
    const float* Wc2w  = (const float*)d_in[17];
    const float* Wc2b  = (const float*)d_in[18];

    float* out    = (float*)d_out;
    float* out_hx = out;
    float* out_he = out + (size_t)N_NODES * H;
    float* out_ha = out_he + (size_t)N_EDGES * H;

    const int* src  = ei;
    const int* tgt  = ei + N_EDGES;
    const int* bsrc = bei;
    const int* btgt = bei + N_BONDS;

    float *p_he0, *p_agg, *p_agg2, *p_tmp;
    unsigned char* p_w;
    cudaGetSymbolAddress((void**)&p_he0,  g_he0);
    cudaGetSymbolAddress((void**)&p_agg,  g_agg);
    cudaGetSymbolAddress((void**)&p_agg2, g_agg2);
    cudaGetSymbolAddress((void**)&p_tmp,  g_tmp);
    cudaGetSymbolAddress((void**)&p_w,    g_wsplit);

    static cudaStream_t s1 = nullptr, s2 = nullptr;
    static cudaEvent_t evStart, evZ, evA, evB, evC;
    if (!s1) {
        cudaStreamCreateWithFlags(&s1, cudaStreamNonBlocking);
        cudaStreamCreateWithFlags(&s2, cudaStreamNonBlocking);
        cudaEventCreateWithFlags(&evStart, cudaEventDisableTiming);
        cudaEventCreateWithFlags(&evZ, cudaEventDisableTiming);
        cudaEventCreateWithFlags(&evA, cudaEventDisableTiming);
        cudaEventCreateWithFlags(&evB, cudaEventDisableTiming);
        cudaEventCreateWithFlags(&evC, cudaEventDisableTiming);
        cudaFuncSetAttribute(mma_gemm<3, 0>, cudaFuncAttributeMaxDynamicSharedMemorySize, SMEM_GEMM_BYTES);
        cudaFuncSetAttribute(mma_gemm<2, 0>, cudaFuncAttributeMaxDynamicSharedMemorySize, SMEM_GEMM_BYTES);
        cudaFuncSetAttribute(mma_gemm<1, 1>, cudaFuncAttributeMaxDynamicSharedMemorySize, SMEM_GEMM_BYTES);
        cudaFuncSetAttribute(mma_gemm<1, 2>, cudaFuncAttributeMaxDynamicSharedMemorySize, SMEM_GEMM_BYTES);
    }

    WSrcs ws;
    ws.p[0] = W_n2e; ws.p[1] = W_n2e + 128 * H; ws.p[2] = W_n2e + 256 * H;
    ws.p[3] = Wc1w;  ws.p[4] = Wc1w + 128 * H;
    ws.p[5] = A1w;   ws.p[6] = A2w;   ws.p[7] = A3w;
    ws.p[8] = Wc2w;  ws.p[9] = Wc2w + 128 * H;
    prep_all<<<640, 256>>>(ws, p_w);

    cudaEventRecord(evStart, 0);
    cudaStreamWaitEvent(s1, evStart, 0);
    cudaStreamWaitEvent(s2, evStart, 0);

    // zero scratch on s1 (concurrent with GEMM1)
    zero_scratch<<<(N_EDGES * H) / 256, 256, 0, s1>>>();
    cudaEventRecord(evZ, s1);

    // hx part1 = x @ Wc2[0:128] (raw) on s2 — no dependencies, hides behind GEMM1
    mma_gemm<1, 1><<<(N_NODES + 127) / 128, 256, SMEM_GEMM_BYTES, s2>>>(
        N_NODES, x, nullptr, nullptr, nullptr, nullptr, p_w + 8 * 65536,
        Wc2b, nullptr, nullptr, nullptr, p_tmp);
    cudaEventRecord(evC, s2);

    // 1) he0 = relu(cat(x[src], x[tgt], edge_attr) @ W_n2e + b)   [main]
    mma_gemm<3, 0><<<(N_EDGES + 127) / 128, 256, SMEM_GEMM_BYTES>>>(
        N_EDGES, x, src, x, tgt, eattr, p_w + 0 * 65536,
        b_n2e, nullptr, nullptr, nullptr, p_he0);
    cudaEventRecord(evA, 0);

    // 4) ha GEMM on s1, concurrent with scatter/he/attention
    cudaStreamWaitEvent(s1, evA, 0);
    mma_gemm<3, 0><<<(N_BONDS + 127) / 128, 256, SMEM_GEMM_BYTES, s1>>>(
        N_BONDS, p_he0, bsrc, p_he0, btgt, battr, p_w + 5 * 65536,
        A1b, A2b, A3b, battr, out_ha);
    cudaEventRecord(evB, s1);

    cudaStreamWaitEvent(0, evZ, 0);

    // 2) agg[btgt] += he0[bsrc] * bond_attr
    scatter_bond<<<(N_BONDS * 32) / 256, 256>>>(bsrc, btgt, battr);

    // 3) he = relu(cat(he0, agg) @ Wc1 + b)
    mma_gemm<2, 0><<<(N_EDGES + 127) / 128, 256, SMEM_GEMM_BYTES>>>(
        N_EDGES, p_he0, nullptr, p_agg, nullptr, nullptr, p_w + 3 * 65536,
        Wc1b, nullptr, nullptr, nullptr, out_he);

    // 5) attention beta (caches xj into g_agg, accumulates den)
    attn_beta<<<(N_EDGES * 32) / 256, 256>>>(x, src, tgt, out_he, attnw, attnb);

    // 5b) invert denominators
    inv_den<<<(N_NODES * NH + 255) / 256, 256>>>();

    // 6) agg2[tgt] += alpha * xj
    attn_scatter<<<(N_EDGES * 32) / 256, 256>>>(tgt);

    // 7) hx = relu(agg2 @ Wc2[128:256] + b + tmp)
    cudaStreamWaitEvent(0, evC, 0);
    mma_gemm<1, 2><<<(N_NODES + 127) / 128, 256, SMEM_GEMM_BYTES>>>(
        N_NODES, p_agg2, nullptr, nullptr, nullptr, nullptr, p_w + 9 * 65536,
        Wc2b, nullptr, nullptr, p_tmp, out_hx);

    cudaStreamWaitEvent(0, evB, 0);
}